// round 1
// baseline (speedup 1.0000x reference)
#include <cuda_runtime.h>

// ---------------- problem constants ----------------
#define C_CH   256
#define H_F    50
#define W_F    50
#define N_IMG  2
#define NROI   1000
#define K_DIM  12544      // 256 * 49
#define HID    1024
#define NCLS   81

// ---------------- scratch (device globals; no allocs allowed) ----------------
__device__ float g_feat[N_IMG * H_F * W_F * C_CH];   // NHWC features (5.1 MB)
__device__ float g_x[NROI * K_DIM];                  // pooled, K-order = p*256 + c (50 MB)
__device__ float g_h1[NROI * HID];
__device__ float g_c [NROI * HID];
__device__ float g_h2[NROI * HID];

// ---------------- 1) NCHW -> NHWC transpose ----------------
__global__ void nchw2nhwc(const float* __restrict__ f) {
    int idx = blockIdx.x * 256 + threadIdx.x;
    const int total = N_IMG * H_F * W_F * C_CH;
    if (idx >= total) return;
    int c = idx & 255;
    int rest = idx >> 8;
    int w = rest % W_F; rest /= W_F;
    int h = rest % H_F;
    int n = rest / H_F;
    g_feat[idx] = f[((n * C_CH + c) * H_F + h) * W_F + w];
}

// ---------------- 2) RoIAlign (torchvision, aligned=False, SR=2) ----------------
// block = one roi, thread = one channel. Writes x[k][p*256 + c] (coalesced).
__global__ void roi_align_kernel(const float* __restrict__ props) {
    int k = blockIdx.x;
    int c = threadIdx.x;

    __shared__ int   s_i0y[14], s_i1y[14], s_i0x[14], s_i1x[14];
    __shared__ float s_wly[14], s_why[14], s_wlx[14], s_whx[14];
    __shared__ int   s_vy[14], s_vx[14];
    __shared__ int   s_b;

    if (c == 0) s_b = (int)props[k * 5];
    if (c < 28) {
        int axis = c / 14;     // 0: y-axis, 1: x-axis
        int q    = c % 14;     // sample index 0..13 (bin*2 + sub)
        float lo = props[k * 5 + (axis ? 1 : 2)] * (1.0f / 16.0f);
        float hi = props[k * 5 + (axis ? 3 : 4)] * (1.0f / 16.0f);
        float ext = fmaxf(hi - lo, 1.0f);
        float bin = ext / 7.0f;
        int p = q >> 1, s = q & 1;
        float t = (float)p + ((float)s + 0.5f) * 0.5f;
        float y = lo + t * bin;
        int valid = (y > -1.0f) && (y < 50.0f);
        float yc = fminf(fmaxf(y, 0.0f), 49.0f);
        int i0 = (int)floorf(yc);
        int i1 = min(i0 + 1, 49);
        float whi = yc - (float)i0;
        float wlo = 1.0f - whi;
        if (axis == 0) { s_vy[q]=valid; s_i0y[q]=i0; s_i1y[q]=i1; s_wly[q]=wlo; s_why[q]=whi; }
        else           { s_vx[q]=valid; s_i0x[q]=i0; s_i1x[q]=i1; s_wlx[q]=wlo; s_whx[q]=whi; }
    }
    __syncthreads();

    const float* F = g_feat + (size_t)s_b * (H_F * W_F * C_CH) + c;
    float* out = g_x + (size_t)k * K_DIM + c;

    #pragma unroll 1
    for (int p = 0; p < 49; p++) {
        int by = p / 7, bx = p % 7;
        float acc = 0.0f;
        #pragma unroll
        for (int sy = 0; sy < 2; sy++) {
            int qy = by * 2 + sy;
            if (!s_vy[qy]) continue;                 // uniform across block
            const float* Fy0 = F + s_i0y[qy] * (W_F * C_CH);
            const float* Fy1 = F + s_i1y[qy] * (W_F * C_CH);
            float wly = s_wly[qy], why = s_why[qy];
            #pragma unroll
            for (int sx = 0; sx < 2; sx++) {
                int qx = bx * 2 + sx;
                if (!s_vx[qx]) continue;             // uniform across block
                int o0 = s_i0x[qx] * C_CH, o1 = s_i1x[qx] * C_CH;
                acc += wly * (s_wlx[qx] * Fy0[o0] + s_whx[qx] * Fy0[o1])
                     + why * (s_wlx[qx] * Fy1[o0] + s_whx[qx] * Fy1[o1]);
            }
        }
        out[p * C_CH] = acc * 0.25f;
    }
}

// ---------------- 3) fp32 SIMT GEMM, 128x128 tile, 8 K-depth, 256 threads ----------------
// C = relu(A @ B + bias). blockIdx.z selects (B, bias, C) so both big GEMMs
// run in ONE launch (128 blocks = one wave). permB maps our K-order
// (kidx = p*256 + c) onto the weight row order (row = c*49 + p).
__global__ __launch_bounds__(256) void sgemm128(
    const float* __restrict__ A,
    const float* __restrict__ Ba, const float* __restrict__ Bb,
    const float* __restrict__ biasa, const float* __restrict__ biasb,
    float* __restrict__ Ca, float* __restrict__ Cb,
    int M, int N, int K, int permB)
{
    const float* B    = blockIdx.z ? Bb    : Ba;
    const float* bias = blockIdx.z ? biasb : biasa;
    float*       C    = blockIdx.z ? Cb    : Ca;

    __shared__ float As[8][128];
    __shared__ float Bs[8][128];

    int tid  = threadIdx.x;
    int row0 = blockIdx.y * 128;
    int col0 = blockIdx.x * 128;

    int aRow = tid >> 1;            // 0..127
    int aCol = (tid & 1) * 4;       // 0 or 4
    int bRow = tid >> 5;            // 0..7
    int bCol = (tid & 31) * 4;      // 0..124

    float acc[8][8] = {};
    int tr = (tid >> 4) * 8;
    int tc = (tid & 15) * 8;

    const float* Aptr = A + (size_t)(row0 + aRow) * K;
    bool aValid = (row0 + aRow) < M;

    for (int k0 = 0; k0 < K; k0 += 8) {
        float4 av = make_float4(0.f, 0.f, 0.f, 0.f);
        if (aValid) av = *(const float4*)(Aptr + k0 + aCol);
        As[aCol + 0][aRow] = av.x;
        As[aCol + 1][aRow] = av.y;
        As[aCol + 2][aRow] = av.z;
        As[aCol + 3][aRow] = av.w;

        int kr = k0 + bRow;
        int brow = permB ? ((kr & 255) * 49 + (kr >> 8)) : kr;
        *(float4*)&Bs[bRow][bCol] = *(const float4*)(B + (size_t)brow * N + col0 + bCol);
        __syncthreads();

        #pragma unroll
        for (int kk = 0; kk < 8; kk++) {
            float4 a0 = *(const float4*)&As[kk][tr];
            float4 a1 = *(const float4*)&As[kk][tr + 4];
            float4 b0 = *(const float4*)&Bs[kk][tc];
            float4 b1 = *(const float4*)&Bs[kk][tc + 4];
            float ar[8] = {a0.x, a0.y, a0.z, a0.w, a1.x, a1.y, a1.z, a1.w};
            float br[8] = {b0.x, b0.y, b0.z, b0.w, b1.x, b1.y, b1.z, b1.w};
            #pragma unroll
            for (int i = 0; i < 8; i++)
                #pragma unroll
                for (int j = 0; j < 8; j++)
                    acc[i][j] += ar[i] * br[j];
        }
        __syncthreads();
    }

    #pragma unroll
    for (int i = 0; i < 8; i++) {
        int r = row0 + tr + i;
        if (r >= M) break;
        #pragma unroll
        for (int j = 0; j < 8; j++) {
            float v = acc[i][j] + bias[col0 + tc + j];
            C[(size_t)r * N + col0 + tc + j] = fmaxf(v, 0.0f);
        }
    }
}

// ---------------- 4) output heads: bbox (h2 @ W3 + b3) and logits (c @ Wc2 + bc2) ----------------
__global__ void heads_kernel(const float* __restrict__ W3,  const float* __restrict__ b3,
                             const float* __restrict__ Wc2, const float* __restrict__ bc2,
                             float* __restrict__ out)
{
    int k = blockIdx.x;
    __shared__ float sh[HID], sc[HID];
    for (int i = threadIdx.x; i < HID; i += blockDim.x) {
        sh[i] = g_h2[(size_t)k * HID + i];
        sc[i] = g_c [(size_t)k * HID + i];
    }
    __syncthreads();

    for (int j = threadIdx.x; j < 4 + NCLS; j += blockDim.x) {
        if (j < 4) {
            float acc = b3[j];
            #pragma unroll 4
            for (int kk = 0; kk < HID; kk++) acc += sh[kk] * W3[kk * 4 + j];
            out[k * 4 + j] = acc;
        } else {
            int jj = j - 4;
            float acc = bc2[jj];
            #pragma unroll 4
            for (int kk = 0; kk < HID; kk++) acc += sc[kk] * Wc2[kk * NCLS + jj];
            out[NROI * 4 + k * NCLS + jj] = acc;
        }
    }
}

// ---------------- launch ----------------
extern "C" void kernel_launch(void* const* d_in, const int* in_sizes, int n_in,
                              void* d_out, int out_size)
{
    const float* features  = (const float*)d_in[0];
    const float* proposals = (const float*)d_in[1];
    const float* W1  = (const float*)d_in[2];
    const float* b1  = (const float*)d_in[3];
    const float* W2  = (const float*)d_in[4];
    const float* b2  = (const float*)d_in[5];
    const float* W3  = (const float*)d_in[6];
    const float* b3  = (const float*)d_in[7];
    const float* Wc1 = (const float*)d_in[8];
    const float* bc1 = (const float*)d_in[9];
    const float* Wc2 = (const float*)d_in[10];
    const float* bc2 = (const float*)d_in[11];
    float* out = (float*)d_out;

    float *xg, *h1g, *cg, *h2g;
    cudaGetSymbolAddress((void**)&xg,  g_x);
    cudaGetSymbolAddress((void**)&h1g, g_h1);
    cudaGetSymbolAddress((void**)&cg,  g_c);
    cudaGetSymbolAddress((void**)&h2g, g_h2);

    const int tot = N_IMG * H_F * W_F * C_CH;
    nchw2nhwc<<<(tot + 255) / 256, 256>>>(features);
    roi_align_kernel<<<NROI, 256>>>(proposals);

    // both K=12544 GEMMs in one launch: z=0 -> h1 = relu(x@W1+b1), z=1 -> c = relu(x@Wc1+bc1)
    sgemm128<<<dim3(HID / 128, (NROI + 127) / 128, 2), 256>>>(
        xg, W1, Wc1, b1, bc1, h1g, cg, NROI, HID, K_DIM, 1);

    // h2 = relu(h1 @ W2 + b2)
    sgemm128<<<dim3(HID / 128, (NROI + 127) / 128, 1), 256>>>(
        h1g, W2, W2, b2, b2, h2g, h2g, NROI, HID, HID, 0);

    heads_kernel<<<NROI, 128>>>(W3, b3, Wc2, bc2, out);
}

// round 3
// speedup vs baseline: 2.6316x; 2.6316x over previous
#include <cuda_runtime.h>
#include <cuda_bf16.h>
#include <cstdint>

// ---------------- problem constants ----------------
#define C_CH   256
#define H_F    50
#define W_F    50
#define N_IMG  2
#define NROI   1000
#define MPAD   1024
#define KB     12544          // 256*49
#define K3     (3*KB)         // 37632  (split-bf16 tripled K)
#define HID    1024
#define H3     (3*HID)        // 3072
#define NCLS   81

// ---------------- scratch (device globals; no allocs) ----------------
__device__ float          g_feat[N_IMG * H_F * W_F * C_CH];  // NHWC fp32
__device__ __nv_bfloat16  g_x3 [MPAD * K3];    // A3 = [hi | lo | hi]
__device__ __nv_bfloat16  g_W1 [HID * K3];     // B3 = [hi | hi | lo], [n][k']
__device__ __nv_bfloat16  g_Wc1[HID * K3];
__device__ __nv_bfloat16  g_W2 [HID * H3];
__device__ __nv_bfloat16  g_h13[MPAD * H3];    // h1 triple [hi | lo | hi]
__device__ float          g_c  [NROI * HID];
__device__ float          g_h2 [NROI * HID];
__device__ float          g_W3t [4 * HID];     // transposed head weights
__device__ float          g_Wc2t[NCLS * HID];

// ---------------- small PTX helpers ----------------
__device__ __forceinline__ uint32_t smem_u32(const void* p) {
    uint32_t a;
    asm("{ .reg .u64 t; cvta.to.shared.u64 t, %1; cvt.u32.u64 %0, t; }" : "=r"(a) : "l"(p));
    return a;
}
__device__ __forceinline__ void cp16(uint32_t d, const void* s) {
    asm volatile("cp.async.cg.shared.global [%0], [%1], 16;" :: "r"(d), "l"(s));
}
#define CP_COMMIT() asm volatile("cp.async.commit_group;" ::: "memory")
#define CP_WAIT2()  asm volatile("cp.async.wait_group 2;"  ::: "memory")

#define LDSM4(f, addr) \
    asm volatile("ldmatrix.sync.aligned.m8n8.x4.shared.b16 {%0,%1,%2,%3}, [%4];" \
        : "=r"((f)[0]), "=r"((f)[1]), "=r"((f)[2]), "=r"((f)[3]) : "r"(addr))

#define MMA16816(d, a, bl, bh) \
    asm volatile("mma.sync.aligned.m16n8k16.row.col.f32.bf16.bf16.f32 " \
        "{%0,%1,%2,%3},{%4,%5,%6,%7},{%8,%9},{%0,%1,%2,%3};" \
        : "+f"((d)[0]), "+f"((d)[1]), "+f"((d)[2]), "+f"((d)[3]) \
        : "r"((a)[0]), "r"((a)[1]), "r"((a)[2]), "r"((a)[3]), "r"(bl), "r"(bh))

// ---------------- 1) NCHW -> NHWC ----------------
__global__ void nchw2nhwc(const float* __restrict__ f) {
    int idx = blockIdx.x * 256 + threadIdx.x;
    const int total = N_IMG * H_F * W_F * C_CH;
    if (idx >= total) return;
    int c = idx & 255;
    int rest = idx >> 8;
    int w = rest % W_F; rest /= W_F;
    int h = rest % H_F;
    int n = rest / H_F;
    g_feat[idx] = f[((n * C_CH + c) * H_F + h) * W_F + w];
}

// ---------------- 2) RoIAlign -> triple split-bf16 x3 ----------------
__global__ void roi_align_kernel(const float* __restrict__ props) {
    int k = blockIdx.x;
    int c = threadIdx.x;

    __shared__ int   s_i0y[14], s_i1y[14], s_i0x[14], s_i1x[14];
    __shared__ float s_wly[14], s_why[14], s_wlx[14], s_whx[14];
    __shared__ int   s_vy[14], s_vx[14];
    __shared__ int   s_b;

    if (c == 0) s_b = (int)props[k * 5];
    if (c < 28) {
        int axis = c / 14;
        int q    = c % 14;
        float lo = props[k * 5 + (axis ? 1 : 2)] * (1.0f / 16.0f);
        float hi = props[k * 5 + (axis ? 3 : 4)] * (1.0f / 16.0f);
        float ext = fmaxf(hi - lo, 1.0f);
        float bin = ext / 7.0f;
        int p = q >> 1, s = q & 1;
        float t = (float)p + ((float)s + 0.5f) * 0.5f;
        float y = lo + t * bin;
        int valid = (y > -1.0f) && (y < 50.0f);
        float yc = fminf(fmaxf(y, 0.0f), 49.0f);
        int i0 = (int)floorf(yc);
        int i1 = min(i0 + 1, 49);
        float whi = yc - (float)i0;
        float wlo = 1.0f - whi;
        if (axis == 0) { s_vy[q]=valid; s_i0y[q]=i0; s_i1y[q]=i1; s_wly[q]=wlo; s_why[q]=whi; }
        else           { s_vx[q]=valid; s_i0x[q]=i0; s_i1x[q]=i1; s_wlx[q]=wlo; s_whx[q]=whi; }
    }
    __syncthreads();

    const float* F = g_feat + (size_t)s_b * (H_F * W_F * C_CH) + c;
    size_t ob = (size_t)k * K3 + c;

    #pragma unroll 1
    for (int p = 0; p < 49; p++) {
        int by = p / 7, bx = p % 7;
        float acc = 0.0f;
        #pragma unroll
        for (int sy = 0; sy < 2; sy++) {
            int qy = by * 2 + sy;
            if (!s_vy[qy]) continue;
            const float* Fy0 = F + s_i0y[qy] * (W_F * C_CH);
            const float* Fy1 = F + s_i1y[qy] * (W_F * C_CH);
            float wly = s_wly[qy], why = s_why[qy];
            #pragma unroll
            for (int sx = 0; sx < 2; sx++) {
                int qx = bx * 2 + sx;
                if (!s_vx[qx]) continue;
                int o0 = s_i0x[qx] * C_CH, o1 = s_i1x[qx] * C_CH;
                acc += wly * (s_wlx[qx] * Fy0[o0] + s_whx[qx] * Fy0[o1])
                     + why * (s_wlx[qx] * Fy1[o0] + s_whx[qx] * Fy1[o1]);
            }
        }
        float v = acc * 0.25f;
        __nv_bfloat16 h = __float2bfloat16(v);
        __nv_bfloat16 l = __float2bfloat16(v - __bfloat162float(h));
        size_t o = ob + (size_t)p * C_CH;
        g_x3[o]          = h;   // seg0: hi
        g_x3[o + KB]     = l;   // seg1: lo
        g_x3[o + 2*KB]   = h;   // seg2: hi
    }
}

// ---------------- 3a) W1/Wc1 prep: W[c*49+p][n] -> B3[n][p*256+c] = [hi|hi|lo] ----------------
__global__ __launch_bounds__(256) void prep_big(const float* __restrict__ W,
                                                __nv_bfloat16* __restrict__ out) {
    __shared__ float s[64][65];
    int p  = blockIdx.z;
    int c0 = blockIdx.y << 6;
    int n0 = blockIdx.x << 6;
    for (int i = threadIdx.x; i < 4096; i += 256) {
        int ci = i >> 6, ni = i & 63;
        s[ci][ni] = W[(size_t)((c0 + ci) * 49 + p) * HID + n0 + ni];
    }
    __syncthreads();
    for (int i = threadIdx.x; i < 4096; i += 256) {
        int ni = i >> 6, ci = i & 63;
        float v = s[ci][ni];
        __nv_bfloat16 h = __float2bfloat16(v);
        __nv_bfloat16 l = __float2bfloat16(v - __bfloat162float(h));
        size_t o = (size_t)(n0 + ni) * K3 + p * 256 + c0 + ci;
        out[o]        = h;   // seg0: hi
        out[o + KB]   = h;   // seg1: hi
        out[o + 2*KB] = l;   // seg2: lo
    }
}

// ---------------- 3b) W2 prep: W2[k][n] -> B3[n][k'] = [hi|hi|lo] ----------------
__global__ __launch_bounds__(256) void prep_w2(const float* __restrict__ W) {
    __shared__ float s[64][65];
    int k0 = blockIdx.y << 6;
    int n0 = blockIdx.x << 6;
    for (int i = threadIdx.x; i < 4096; i += 256) {
        int ki = i >> 6, ni = i & 63;
        s[ki][ni] = W[(size_t)(k0 + ki) * HID + n0 + ni];
    }
    __syncthreads();
    for (int i = threadIdx.x; i < 4096; i += 256) {
        int ni = i >> 6, ki = i & 63;
        float v = s[ki][ni];
        __nv_bfloat16 h = __float2bfloat16(v);
        __nv_bfloat16 l = __float2bfloat16(v - __bfloat162float(h));
        size_t o = (size_t)(n0 + ni) * H3 + k0 + ki;
        g_W2[o]           = h;
        g_W2[o + HID]     = h;
        g_W2[o + 2*HID]   = l;
    }
}

// ---------------- 3c) head-weight transposes ----------------
__global__ void prep_heads(const float* __restrict__ W3, const float* __restrict__ Wc2) {
    int i = blockIdx.x * 256 + threadIdx.x;
    if (i < 4 * HID) {
        g_W3t[(i & 3) * HID + (i >> 2)] = W3[i];
    }
    int j = i - 4 * HID;
    if (j >= 0 && j < NCLS * HID) {
        g_Wc2t[(j % NCLS) * HID + (j / NCLS)] = Wc2[j];
    }
}

// ---------------- 4) HMMA bf16 GEMM: 128x128 tile, BK=32, 4-stage cp.async ----------------
#define BM 128
#define BN 128
#define BK 32
#define NSTAGE 4
#define ROWB 80                        // 32 bf16 (64B) + 16B pad -> conflict-free ldmatrix
#define AB_OFF (128 * ROWB)            // B tile offset within a stage
#define STAGE_BYTES (2 * 128 * ROWB)   // 20480
#define SMEM_TOTAL (NSTAGE * STAGE_BYTES)

__global__ void __launch_bounds__(256, 1) gemm_mma(
    const __nv_bfloat16* __restrict__ A,
    const __nv_bfloat16* __restrict__ B0, const float* __restrict__ bias0,
    const __nv_bfloat16* __restrict__ B1, const float* __restrict__ bias1,
    float* __restrict__ outF0, __nv_bfloat16* __restrict__ outT0,
    float* __restrict__ outF1, __nv_bfloat16* __restrict__ outT1,
    int K)
{
    extern __shared__ char sm[];
    const int tid  = threadIdx.x;
    const int lane = tid & 31;
    const int wid  = tid >> 5;
    const int warp_m = wid >> 2;        // 0..1  (64-row slabs)
    const int warp_n = wid & 3;         // 0..3  (32-col slabs)
    const int row0 = blockIdx.y * BM;
    const int col0 = blockIdx.x * BN;
    const bool z   = (blockIdx.z != 0);

    const __nv_bfloat16* B    = z ? B1 : B0;
    const float*         bias = z ? bias1 : bias0;
    float*               outF = z ? outF1 : outF0;
    __nv_bfloat16*       outT = z ? outT1 : outT0;

    const uint32_t sbase = smem_u32(sm);
    const int nch = K / BK;

    // cp.async mapping: thread -> one row, two 16B chunks of A and of B
    const int ld_r  = tid >> 1;
    const int ld_cb = (tid & 1) * 32;
    const char* gA = (const char*)(A + (size_t)(row0 + ld_r) * K) + ld_cb;
    const char* gB = (const char*)(B + (size_t)(col0 + ld_r) * K) + ld_cb;
    const uint32_t sA_rc = sbase + ld_r * ROWB + ld_cb;
    const uint32_t sB_rc = sbase + AB_OFF + ld_r * ROWB + ld_cb;

    #define ISSUE(st, kc) do {                                  \
        uint32_t da = sA_rc + (st) * STAGE_BYTES;               \
        const char* pa = gA + (size_t)(kc) * (BK * 2);          \
        cp16(da, pa); cp16(da + 16, pa + 16);                   \
        uint32_t db = sB_rc + (st) * STAGE_BYTES;               \
        const char* pb = gB + (size_t)(kc) * (BK * 2);          \
        cp16(db, pb); cp16(db + 16, pb + 16);                   \
        CP_COMMIT();                                            \
    } while (0)

    ISSUE(0, 0); ISSUE(1, 1); ISSUE(2, 2);

    float acc[4][4][4] = {};

    // per-lane ldmatrix offsets (row = lane&15, 16B half = lane>>4)
    const uint32_t lrow = (lane & 15) * ROWB + ((lane >> 4) * 16);

    for (int kc = 0; kc < nch; kc++) {
        CP_WAIT2();
        __syncthreads();
        const int st = kc & (NSTAGE - 1);
        const uint32_t saA = sbase + st * STAGE_BYTES + lrow + (warp_m * 64) * ROWB;
        const uint32_t saB = sbase + st * STAGE_BYTES + AB_OFF + lrow + (warp_n * 32) * ROWB;

        #pragma unroll
        for (int ks = 0; ks < 2; ks++) {
            uint32_t af[4][4], bfr[2][4];
            #pragma unroll
            for (int mt = 0; mt < 4; mt++)
                LDSM4(af[mt], saA + mt * (16 * ROWB) + ks * 32);
            #pragma unroll
            for (int nt2 = 0; nt2 < 2; nt2++)
                LDSM4(bfr[nt2], saB + nt2 * (16 * ROWB) + ks * 32);
            #pragma unroll
            for (int mt = 0; mt < 4; mt++)
                #pragma unroll
                for (int nt = 0; nt < 4; nt++)
                    MMA16816(acc[mt][nt], af[mt],
                             bfr[nt >> 1][nt & 1], bfr[nt >> 1][(nt & 1) + 2]);
        }

        if (kc + NSTAGE - 1 < nch) {
            ISSUE((kc + NSTAGE - 1) & (NSTAGE - 1), kc + NSTAGE - 1);
        } else {
            CP_COMMIT();   // keep group accounting uniform for CP_WAIT2
        }
    }

    // ---------------- epilogue ----------------
    #pragma unroll
    for (int mt = 0; mt < 4; mt++) {
        #pragma unroll
        for (int half = 0; half < 2; half++) {
            int r = row0 + warp_m * 64 + mt * 16 + (lane >> 2) + half * 8;
            if (r >= NROI) continue;
            #pragma unroll
            for (int nt = 0; nt < 4; nt++) {
                int ccol = col0 + warp_n * 32 + nt * 8 + (lane & 3) * 2;
                float v0 = fmaxf(acc[mt][nt][half * 2 + 0] + bias[ccol],     0.0f);
                float v1 = fmaxf(acc[mt][nt][half * 2 + 1] + bias[ccol + 1], 0.0f);
                if (outF) {
                    outF[(size_t)r * HID + ccol]     = v0;
                    outF[(size_t)r * HID + ccol + 1] = v1;
                }
                if (outT) {
                    __nv_bfloat162 hv, lv;
                    hv.x = __float2bfloat16(v0);
                    hv.y = __float2bfloat16(v1);
                    lv.x = __float2bfloat16(v0 - __bfloat162float(hv.x));
                    lv.y = __float2bfloat16(v1 - __bfloat162float(hv.y));
                    size_t rb = (size_t)r * H3;
                    *(__nv_bfloat162*)&outT[rb + ccol]           = hv;  // seg0: hi
                    *(__nv_bfloat162*)&outT[rb + HID + ccol]     = lv;  // seg1: lo
                    *(__nv_bfloat162*)&outT[rb + 2*HID + ccol]   = hv;  // seg2: hi
                }
            }
        }
    }
    #undef ISSUE
}

// ---------------- 5) heads: warp per (roi, out-col), coalesced transposed weights ----------------
__global__ void heads_kernel(const float* __restrict__ b3, const float* __restrict__ bc2,
                             float* __restrict__ out)
{
    int k = blockIdx.x;
    int lane = threadIdx.x & 31;
    int wid  = threadIdx.x >> 5;          // 4 warps
    __shared__ float sh[HID], sc[HID];
    for (int i = threadIdx.x; i < HID; i += blockDim.x) {
        sh[i] = g_h2[(size_t)k * HID + i];
        sc[i] = g_c [(size_t)k * HID + i];
    }
    __syncthreads();

    for (int j = wid; j < 4 + NCLS; j += 4) {
        const float* wrow;
        const float* src;
        float bv;
        if (j < 4) { wrow = g_W3t  + (size_t)j * HID;       src = sh; bv = b3[j]; }
        else       { wrow = g_Wc2t + (size_t)(j - 4) * HID; src = sc; bv = bc2[j - 4]; }
        float a = 0.0f;
        #pragma unroll 8
        for (int kk = lane; kk < HID; kk += 32) a += src[kk] * wrow[kk];
        #pragma unroll
        for (int o = 16; o > 0; o >>= 1) a += __shfl_xor_sync(0xFFFFFFFFu, a, o);
        if (lane == 0) {
            if (j < 4) out[k * 4 + j] = a + bv;
            else       out[NROI * 4 + k * NCLS + (j - 4)] = a + bv;
        }
    }
}

// ---------------- launch ----------------
extern "C" void kernel_launch(void* const* d_in, const int* in_sizes, int n_in,
                              void* d_out, int out_size)
{
    const float* features  = (const float*)d_in[0];
    const float* proposals = (const float*)d_in[1];
    const float* W1  = (const float*)d_in[2];
    const float* b1  = (const float*)d_in[3];
    const float* W2  = (const float*)d_in[4];
    const float* b2  = (const float*)d_in[5];
    const float* W3  = (const float*)d_in[6];
    const float* b3  = (const float*)d_in[7];
    const float* Wc1 = (const float*)d_in[8];
    const float* bc1 = (const float*)d_in[9];
    const float* Wc2 = (const float*)d_in[10];
    const float* bc2 = (const float*)d_in[11];
    float* out = (float*)d_out;

    cudaFuncSetAttribute(gemm_mma, cudaFuncAttributeMaxDynamicSharedMemorySize, SMEM_TOTAL);

    __nv_bfloat16 *x3, *w1p, *wc1p, *w2p, *h13;
    float *cg, *h2g;
    cudaGetSymbolAddress((void**)&x3,   g_x3);
    cudaGetSymbolAddress((void**)&w1p,  g_W1);
    cudaGetSymbolAddress((void**)&wc1p, g_Wc1);
    cudaGetSymbolAddress((void**)&w2p,  g_W2);
    cudaGetSymbolAddress((void**)&h13,  g_h13);
    cudaGetSymbolAddress((void**)&cg,   g_c);
    cudaGetSymbolAddress((void**)&h2g,  g_h2);

    const int tot = N_IMG * H_F * W_F * C_CH;
    nchw2nhwc<<<(tot + 255) / 256, 256>>>(features);
    roi_align_kernel<<<NROI, 256>>>(proposals);

    prep_big<<<dim3(16, 4, 49), 256>>>(W1,  w1p);
    prep_big<<<dim3(16, 4, 49), 256>>>(Wc1, wc1p);
    prep_w2 <<<dim3(16, 16),    256>>>(W2);
    prep_heads<<<(4 * HID + NCLS * HID + 255) / 256, 256>>>(W3, Wc2);

    // GEMM1 fused: z=0 -> h1 (triple bf16), z=1 -> c (f32)
    gemm_mma<<<dim3(8, 8, 2), 256, SMEM_TOTAL>>>(
        x3, w1p, b1, wc1p, bc1,
        nullptr, h13, cg, nullptr, K3);

    // GEMM2: h2 = relu(h1 @ W2 + b2)
    gemm_mma<<<dim3(8, 8, 1), 256, SMEM_TOTAL>>>(
        h13, w2p, b2, w2p, b2,
        h2g, nullptr, nullptr, nullptr, H3);

    heads_kernel<<<NROI, 128>>>(b3, bc2, out);
}

// round 4
// speedup vs baseline: 2.9710x; 1.1290x over previous
#include <cuda_runtime.h>
#include <cuda_bf16.h>
#include <cstdint>

// ---------------- problem constants ----------------
#define C_CH   256
#define H_F    50
#define W_F    50
#define N_IMG  2
#define NROI   1000
#define MPAD   1024
#define KB     12544          // 256*49
#define HID    1024
#define NCLS   81

// ---------------- scratch (device globals; no allocs) ----------------
__device__ float          g_feat[N_IMG * H_F * W_F * C_CH];  // NHWC fp32
__device__ __nv_bfloat16  g_xhi[MPAD * KB];
__device__ __nv_bfloat16  g_xlo[MPAD * KB];
__device__ __nv_bfloat16  g_W1hi [HID * KB];   // [n][k], k-order = p*256+c
__device__ __nv_bfloat16  g_W1lo [HID * KB];
__device__ __nv_bfloat16  g_Wc1hi[HID * KB];
__device__ __nv_bfloat16  g_Wc1lo[HID * KB];
__device__ __nv_bfloat16  g_W2hi [HID * HID];
__device__ __nv_bfloat16  g_W2lo [HID * HID];
__device__ __nv_bfloat16  g_h1hi[MPAD * HID];
__device__ __nv_bfloat16  g_h1lo[MPAD * HID];
__device__ float          g_c  [NROI * HID];
__device__ float          g_h2 [NROI * HID];
__device__ float          g_W3t [4 * HID];     // transposed head weights
__device__ float          g_Wc2t[NCLS * HID];

// ---------------- small PTX helpers ----------------
__device__ __forceinline__ uint32_t smem_u32(const void* p) {
    uint32_t a;
    asm("{ .reg .u64 t; cvta.to.shared.u64 t, %1; cvt.u32.u64 %0, t; }" : "=r"(a) : "l"(p));
    return a;
}
__device__ __forceinline__ void cp16(uint32_t d, const void* s) {
    asm volatile("cp.async.cg.shared.global [%0], [%1], 16;" :: "r"(d), "l"(s));
}
#define CP_COMMIT() asm volatile("cp.async.commit_group;" ::: "memory")
#define CP_WAIT2()  asm volatile("cp.async.wait_group 2;"  ::: "memory")

#define LDSM4(f, addr) \
    asm volatile("ldmatrix.sync.aligned.m8n8.x4.shared.b16 {%0,%1,%2,%3}, [%4];" \
        : "=r"((f)[0]), "=r"((f)[1]), "=r"((f)[2]), "=r"((f)[3]) : "r"(addr))

#define MMA16816(d, a, bl, bh) \
    asm volatile("mma.sync.aligned.m16n8k16.row.col.f32.bf16.bf16.f32 " \
        "{%0,%1,%2,%3},{%4,%5,%6,%7},{%8,%9},{%0,%1,%2,%3};" \
        : "+f"((d)[0]), "+f"((d)[1]), "+f"((d)[2]), "+f"((d)[3]) \
        : "r"((a)[0]), "r"((a)[1]), "r"((a)[2]), "r"((a)[3]), "r"(bl), "r"(bh))

// ---------------- 1) NCHW -> NHWC ----------------
__global__ void nchw2nhwc(const float* __restrict__ f) {
    int idx = blockIdx.x * 256 + threadIdx.x;
    const int total = N_IMG * H_F * W_F * C_CH;
    if (idx >= total) return;
    int c = idx & 255;
    int rest = idx >> 8;
    int w = rest % W_F; rest /= W_F;
    int h = rest % H_F;
    int n = rest / H_F;
    g_feat[idx] = f[((n * C_CH + c) * H_F + h) * W_F + w];
}

// ---------------- 2) RoIAlign -> split-bf16 (hi/lo) ----------------
__global__ void roi_align_kernel(const float* __restrict__ props) {
    int k = blockIdx.x;
    int c = threadIdx.x;

    __shared__ int   s_i0y[14], s_i1y[14], s_i0x[14], s_i1x[14];
    __shared__ float s_wly[14], s_why[14], s_wlx[14], s_whx[14];
    __shared__ int   s_vy[14], s_vx[14];
    __shared__ int   s_b;

    if (c == 0) s_b = (int)props[k * 5];
    if (c < 28) {
        int axis = c / 14;
        int q    = c % 14;
        float lo = props[k * 5 + (axis ? 1 : 2)] * (1.0f / 16.0f);
        float hi = props[k * 5 + (axis ? 3 : 4)] * (1.0f / 16.0f);
        float ext = fmaxf(hi - lo, 1.0f);
        float bin = ext / 7.0f;
        int p = q >> 1, s = q & 1;
        float t = (float)p + ((float)s + 0.5f) * 0.5f;
        float y = lo + t * bin;
        int valid = (y > -1.0f) && (y < 50.0f);
        float yc = fminf(fmaxf(y, 0.0f), 49.0f);
        int i0 = (int)floorf(yc);
        int i1 = min(i0 + 1, 49);
        float whi = yc - (float)i0;
        float wlo = 1.0f - whi;
        if (axis == 0) { s_vy[q]=valid; s_i0y[q]=i0; s_i1y[q]=i1; s_wly[q]=wlo; s_why[q]=whi; }
        else           { s_vx[q]=valid; s_i0x[q]=i0; s_i1x[q]=i1; s_wlx[q]=wlo; s_whx[q]=whi; }
    }
    __syncthreads();

    const float* F = g_feat + (size_t)s_b * (H_F * W_F * C_CH) + c;
    size_t ob = (size_t)k * KB + c;

    #pragma unroll 1
    for (int p = 0; p < 49; p++) {
        int by = p / 7, bx = p % 7;
        float acc = 0.0f;
        #pragma unroll
        for (int sy = 0; sy < 2; sy++) {
            int qy = by * 2 + sy;
            if (!s_vy[qy]) continue;
            const float* Fy0 = F + s_i0y[qy] * (W_F * C_CH);
            const float* Fy1 = F + s_i1y[qy] * (W_F * C_CH);
            float wly = s_wly[qy], why = s_why[qy];
            #pragma unroll
            for (int sx = 0; sx < 2; sx++) {
                int qx = bx * 2 + sx;
                if (!s_vx[qx]) continue;
                int o0 = s_i0x[qx] * C_CH, o1 = s_i1x[qx] * C_CH;
                acc += wly * (s_wlx[qx] * Fy0[o0] + s_whx[qx] * Fy0[o1])
                     + why * (s_wlx[qx] * Fy1[o0] + s_whx[qx] * Fy1[o1]);
            }
        }
        float v = acc * 0.25f;
        __nv_bfloat16 h = __float2bfloat16(v);
        __nv_bfloat16 l = __float2bfloat16(v - __bfloat162float(h));
        g_xhi[ob + (size_t)p * C_CH] = h;
        g_xlo[ob + (size_t)p * C_CH] = l;
    }
}

// ---------------- 3a) W1+Wc1 prep (fused): W[c*49+p][n] -> [n][p*256+c] hi/lo ----------------
__global__ __launch_bounds__(256) void prep_big(const float* __restrict__ WA,
                                                const float* __restrict__ WB) {
    __shared__ float s[64][65];
    int zz = blockIdx.z;
    int p  = zz >> 1;
    const float* W = (zz & 1) ? WB : WA;
    __nv_bfloat16* Ohi = (zz & 1) ? g_Wc1hi : g_W1hi;
    __nv_bfloat16* Olo = (zz & 1) ? g_Wc1lo : g_W1lo;
    int c0 = blockIdx.y << 6;
    int n0 = blockIdx.x << 6;
    for (int i = threadIdx.x; i < 4096; i += 256) {
        int ci = i >> 6, ni = i & 63;
        s[ci][ni] = W[(size_t)((c0 + ci) * 49 + p) * HID + n0 + ni];
    }
    __syncthreads();
    for (int i = threadIdx.x; i < 4096; i += 256) {
        int ni = i >> 6, ci = i & 63;
        float v = s[ci][ni];
        __nv_bfloat16 h = __float2bfloat16(v);
        __nv_bfloat16 l = __float2bfloat16(v - __bfloat162float(h));
        size_t o = (size_t)(n0 + ni) * KB + p * 256 + c0 + ci;
        Ohi[o] = h;
        Olo[o] = l;
    }
}

// ---------------- 3b) W2 prep: W2[k][n] -> [n][k] hi/lo ----------------
__global__ __launch_bounds__(256) void prep_w2(const float* __restrict__ W) {
    __shared__ float s[64][65];
    int k0 = blockIdx.y << 6;
    int n0 = blockIdx.x << 6;
    for (int i = threadIdx.x; i < 4096; i += 256) {
        int ki = i >> 6, ni = i & 63;
        s[ki][ni] = W[(size_t)(k0 + ki) * HID + n0 + ni];
    }
    __syncthreads();
    for (int i = threadIdx.x; i < 4096; i += 256) {
        int ni = i >> 6, ki = i & 63;
        float v = s[ki][ni];
        __nv_bfloat16 h = __float2bfloat16(v);
        __nv_bfloat16 l = __float2bfloat16(v - __bfloat162float(h));
        size_t o = (size_t)(n0 + ni) * HID + k0 + ki;
        g_W2hi[o] = h;
        g_W2lo[o] = l;
    }
}

// ---------------- 3c) head-weight transposes ----------------
__global__ void prep_heads(const float* __restrict__ W3, const float* __restrict__ Wc2) {
    int i = blockIdx.x * 256 + threadIdx.x;
    if (i < 4 * HID) {
        g_W3t[(i & 3) * HID + (i >> 2)] = W3[i];
    }
    int j = i - 4 * HID;
    if (j >= 0 && j < NCLS * HID) {
        g_Wc2t[(j % NCLS) * HID + (j / NCLS)] = Wc2[j];
    }
}

// ---------------- 4) HMMA split-bf16 GEMM: 128x128 tile, BK=32 (orig K), 4-tile stages ----------------
// acc = Ahi*Bhi + Alo*Bhi + Ahi*Blo  (lo*lo dropped), all in one accumulator.
#define BM 128
#define BN 128
#define BK 32
#define NSTAGE 4
#define ROWB 80                         // 64B data + 16B pad -> conflict-free ldmatrix
#define TILE_B (128 * ROWB)             // 10240
#define STAGE_BYTES (4 * TILE_B)        // 40960: [Ahi|Alo|Bhi|Blo]
#define SMEM_TOTAL (NSTAGE * STAGE_BYTES)   // 163840

__global__ void __launch_bounds__(256, 1) gemm_mma(
    const __nv_bfloat16* __restrict__ Ahi, const __nv_bfloat16* __restrict__ Alo,
    const __nv_bfloat16* __restrict__ Bh0, const __nv_bfloat16* __restrict__ Bl0,
    const float* __restrict__ bias0,
    const __nv_bfloat16* __restrict__ Bh1, const __nv_bfloat16* __restrict__ Bl1,
    const float* __restrict__ bias1,
    float* __restrict__ outF0, __nv_bfloat16* __restrict__ outHi0, __nv_bfloat16* __restrict__ outLo0,
    float* __restrict__ outF1,
    int K)
{
    extern __shared__ char sm[];
    const int tid  = threadIdx.x;
    const int lane = tid & 31;
    const int wid  = tid >> 5;
    const int warp_m = wid >> 2;        // 0..1  (64-row slabs)
    const int warp_n = wid & 3;         // 0..3  (32-col slabs)
    const int row0 = blockIdx.y * BM;
    const int col0 = blockIdx.x * BN;
    const bool z   = (blockIdx.z != 0);

    const __nv_bfloat16* Bh   = z ? Bh1 : Bh0;
    const __nv_bfloat16* Bl   = z ? Bl1 : Bl0;
    const float*         bias = z ? bias1 : bias0;
    float*               outF = z ? outF1 : outF0;
    __nv_bfloat16*       oHi  = z ? nullptr : outHi0;
    __nv_bfloat16*       oLo  = z ? nullptr : outLo0;

    const uint32_t sbase = smem_u32(sm);
    const int nch = K / BK;

    // cp.async mapping: thread -> one row (of 128), two 16B chunks, in each of 4 tiles
    const int ld_r  = tid >> 1;
    const int ld_cb = (tid & 1) * 32;
    const char* gsrc[4];
    gsrc[0] = (const char*)(Ahi + (size_t)(row0 + ld_r) * K) + ld_cb;
    gsrc[1] = (const char*)(Alo + (size_t)(row0 + ld_r) * K) + ld_cb;
    gsrc[2] = (const char*)(Bh  + (size_t)(col0 + ld_r) * K) + ld_cb;
    gsrc[3] = (const char*)(Bl  + (size_t)(col0 + ld_r) * K) + ld_cb;
    const uint32_t s_rc = sbase + ld_r * ROWB + ld_cb;

    #define ISSUE(st, kc) do {                                  \
        uint32_t dd = s_rc + (st) * STAGE_BYTES;                \
        size_t go = (size_t)(kc) * (BK * 2);                    \
        _Pragma("unroll")                                       \
        for (int t = 0; t < 4; t++) {                           \
            const char* pp = gsrc[t] + go;                      \
            cp16(dd + t * TILE_B, pp);                          \
            cp16(dd + t * TILE_B + 16, pp + 16);                \
        }                                                       \
        CP_COMMIT();                                            \
    } while (0)

    ISSUE(0, 0); ISSUE(1, 1); ISSUE(2, 2);

    float acc[4][4][4] = {};

    // per-lane ldmatrix base (row = lane&15, 16B half = lane>>4)
    const uint32_t lrow = (lane & 15) * ROWB + ((lane >> 4) * 16);

    for (int kc = 0; kc < nch; kc++) {
        CP_WAIT2();
        __syncthreads();
        const int st = kc & (NSTAGE - 1);
        const uint32_t sAh = sbase + st * STAGE_BYTES + lrow + (warp_m * 64) * ROWB;
        const uint32_t sAl = sAh + TILE_B;
        const uint32_t sBh = sbase + st * STAGE_BYTES + 2 * TILE_B + lrow + (warp_n * 32) * ROWB;
        const uint32_t sBl = sBh + TILE_B;

        #pragma unroll
        for (int ks = 0; ks < 2; ks++) {
            uint32_t ah[4][4], ax[4][4], bh[2][4], bl[2][4];
            #pragma unroll
            for (int mt = 0; mt < 4; mt++)
                LDSM4(ah[mt], sAh + mt * (16 * ROWB) + ks * 32);
            #pragma unroll
            for (int nt2 = 0; nt2 < 2; nt2++)
                LDSM4(bh[nt2], sBh + nt2 * (16 * ROWB) + ks * 32);
            #pragma unroll
            for (int mt = 0; mt < 4; mt++)
                #pragma unroll
                for (int nt = 0; nt < 4; nt++)
                    MMA16816(acc[mt][nt], ah[mt],
                             bh[nt >> 1][nt & 1], bh[nt >> 1][(nt & 1) + 2]);
            // lo(A) x hi(B)
            #pragma unroll
            for (int mt = 0; mt < 4; mt++)
                LDSM4(ax[mt], sAl + mt * (16 * ROWB) + ks * 32);
            #pragma unroll
            for (int mt = 0; mt < 4; mt++)
                #pragma unroll
                for (int nt = 0; nt < 4; nt++)
                    MMA16816(acc[mt][nt], ax[mt],
                             bh[nt >> 1][nt & 1], bh[nt >> 1][(nt & 1) + 2]);
            // hi(A) x lo(B)
            #pragma unroll
            for (int nt2 = 0; nt2 < 2; nt2++)
                LDSM4(bl[nt2], sBl + nt2 * (16 * ROWB) + ks * 32);
            #pragma unroll
            for (int mt = 0; mt < 4; mt++)
                #pragma unroll
                for (int nt = 0; nt < 4; nt++)
                    MMA16816(acc[mt][nt], ah[mt],
                             bl[nt >> 1][nt & 1], bl[nt >> 1][(nt & 1) + 2]);
        }

        if (kc + NSTAGE - 1 < nch) {
            ISSUE((kc + NSTAGE - 1) & (NSTAGE - 1), kc + NSTAGE - 1);
        } else {
            CP_COMMIT();   // keep group accounting uniform for CP_WAIT2
        }
    }

    // ---------------- epilogue ----------------
    #pragma unroll
    for (int mt = 0; mt < 4; mt++) {
        #pragma unroll
        for (int half = 0; half < 2; half++) {
            int r = row0 + warp_m * 64 + mt * 16 + (lane >> 2) + half * 8;
            if (r >= NROI) continue;
            #pragma unroll
            for (int nt = 0; nt < 4; nt++) {
                int ccol = col0 + warp_n * 32 + nt * 8 + (lane & 3) * 2;
                float v0 = fmaxf(acc[mt][nt][half * 2 + 0] + bias[ccol],     0.0f);
                float v1 = fmaxf(acc[mt][nt][half * 2 + 1] + bias[ccol + 1], 0.0f);
                if (outF) {
                    outF[(size_t)r * HID + ccol]     = v0;
                    outF[(size_t)r * HID + ccol + 1] = v1;
                }
                if (oHi) {
                    __nv_bfloat162 hv, lv;
                    hv.x = __float2bfloat16(v0);
                    hv.y = __float2bfloat16(v1);
                    lv.x = __float2bfloat16(v0 - __bfloat162float(hv.x));
                    lv.y = __float2bfloat16(v1 - __bfloat162float(hv.y));
                    *(__nv_bfloat162*)&oHi[(size_t)r * HID + ccol] = hv;
                    *(__nv_bfloat162*)&oLo[(size_t)r * HID + ccol] = lv;
                }
            }
        }
    }
    #undef ISSUE
}

// ---------------- 5) heads: 8 rois per block, weight rows shared via registers ----------------
#define HEADS_G 8
__global__ void heads_kernel(const float* __restrict__ b3, const float* __restrict__ bc2,
                             float* __restrict__ out)
{
    extern __shared__ float s[];          // [8*1024 h2 | 8*1024 c]
    float* sh = s;
    float* sc = s + HEADS_G * HID;
    int g0 = blockIdx.x * HEADS_G;
    int lane = threadIdx.x & 31;
    int wid  = threadIdx.x >> 5;          // 8 warps

    for (int i = threadIdx.x; i < HEADS_G * HID; i += blockDim.x) {
        int r = g0 + (i >> 10), kk = i & 1023;
        sh[i] = g_h2[(size_t)r * HID + kk];
        sc[i] = g_c [(size_t)r * HID + kk];
    }
    __syncthreads();

    for (int j = wid; j < 4 + NCLS; j += 8) {
        const float* wrow;
        const float* src;
        float bv;
        if (j < 4) { wrow = g_W3t  + (size_t)j * HID;       src = sh; bv = b3[j]; }
        else       { wrow = g_Wc2t + (size_t)(j - 4) * HID; src = sc; bv = bc2[j - 4]; }
        float a[HEADS_G] = {};
        for (int kk = lane; kk < HID; kk += 32) {
            float wv = wrow[kk];
            #pragma unroll
            for (int g = 0; g < HEADS_G; g++)
                a[g] += src[g * HID + kk] * wv;
        }
        #pragma unroll
        for (int g = 0; g < HEADS_G; g++) {
            #pragma unroll
            for (int o = 16; o > 0; o >>= 1) a[g] += __shfl_xor_sync(0xFFFFFFFFu, a[g], o);
        }
        if (lane == 0) {
            #pragma unroll
            for (int g = 0; g < HEADS_G; g++) {
                int k = g0 + g;
                if (j < 4) out[k * 4 + j] = a[g] + bv;
                else       out[NROI * 4 + k * NCLS + (j - 4)] = a[g] + bv;
            }
        }
    }
}

// ---------------- launch ----------------
extern "C" void kernel_launch(void* const* d_in, const int* in_sizes, int n_in,
                              void* d_out, int out_size)
{
    const float* features  = (const float*)d_in[0];
    const float* proposals = (const float*)d_in[1];
    const float* W1  = (const float*)d_in[2];
    const float* b1  = (const float*)d_in[3];
    const float* W2  = (const float*)d_in[4];
    const float* b2  = (const float*)d_in[5];
    const float* W3  = (const float*)d_in[6];
    const float* b3  = (const float*)d_in[7];
    const float* Wc1 = (const float*)d_in[8];
    const float* bc1 = (const float*)d_in[9];
    const float* Wc2 = (const float*)d_in[10];
    const float* bc2 = (const float*)d_in[11];
    float* out = (float*)d_out;

    cudaFuncSetAttribute(gemm_mma, cudaFuncAttributeMaxDynamicSharedMemorySize, SMEM_TOTAL);
    cudaFuncSetAttribute(heads_kernel, cudaFuncAttributeMaxDynamicSharedMemorySize,
                         2 * HEADS_G * HID * (int)sizeof(float));

    __nv_bfloat16 *xhi, *xlo, *w1hi, *w1lo, *wc1hi, *wc1lo, *w2hi, *w2lo, *h1hi, *h1lo;
    float *cg, *h2g;
    cudaGetSymbolAddress((void**)&xhi,   g_xhi);
    cudaGetSymbolAddress((void**)&xlo,   g_xlo);
    cudaGetSymbolAddress((void**)&w1hi,  g_W1hi);
    cudaGetSymbolAddress((void**)&w1lo,  g_W1lo);
    cudaGetSymbolAddress((void**)&wc1hi, g_Wc1hi);
    cudaGetSymbolAddress((void**)&wc1lo, g_Wc1lo);
    cudaGetSymbolAddress((void**)&w2hi,  g_W2hi);
    cudaGetSymbolAddress((void**)&w2lo,  g_W2lo);
    cudaGetSymbolAddress((void**)&h1hi,  g_h1hi);
    cudaGetSymbolAddress((void**)&h1lo,  g_h1lo);
    cudaGetSymbolAddress((void**)&cg,    g_c);
    cudaGetSymbolAddress((void**)&h2g,   g_h2);

    const int tot = N_IMG * H_F * W_F * C_CH;
    nchw2nhwc<<<(tot + 255) / 256, 256>>>(features);            // launch 1
    roi_align_kernel<<<NROI, 256>>>(proposals);                 // launch 2
    prep_big<<<dim3(16, 4, 98), 256>>>(W1, Wc1);                // launch 3 (fused)
    prep_w2 <<<dim3(16, 16),    256>>>(W2);                     // launch 4
    prep_heads<<<(4 * HID + NCLS * HID + 255) / 256, 256>>>(W3, Wc2);  // launch 5

    // launch 6 (ncu -s 5 target): GEMM1 fused, z=0 -> h1 (hi/lo bf16), z=1 -> c (f32)
    gemm_mma<<<dim3(8, 8, 2), 256, SMEM_TOTAL>>>(
        xhi, xlo,
        w1hi, w1lo, b1,
        wc1hi, wc1lo, bc1,
        nullptr, h1hi, h1lo,
        cg, KB);

    // GEMM2: h2 = relu(h1 @ W2 + b2)
    gemm_mma<<<dim3(8, 8, 1), 256, SMEM_TOTAL>>>(
        h1hi, h1lo,
        w2hi, w2lo, b2,
        w2hi, w2lo, b2,
        h2g, nullptr, nullptr,
        nullptr, HID);

    heads_kernel<<<NROI / HEADS_G, 256, 2 * HEADS_G * HID * (int)sizeof(float)>>>(b3, bc2, out);
}